// round 10
// baseline (speedup 1.0000x reference)
#include <cuda_runtime.h>
#include <cuda_fp16.h>
#include <cstdint>

// DynamicConvolution: B=16, Cin=Cout=128, K=3, H=W=64, pad=1, fp32.
// R10: single fused kernel. CTAs 0..255 each run 5 prep units (input NCHW->NHWC
// fp16 transpose + weight repack, sample-major) then all 512 CTAs spin on a
// per-sample counter before running the R9 conv mainloop (fp16 m16n8k16,
// K-chunk 64, 3-stage cp.async, 2 CTAs/SM). Deadlock-free: workers finish all
// prep before any wait; counters zeroed via capturable cudaMemsetAsync.

#define BB 16
#define CI 128
#define CO 128
#define HW 4096

__device__ __half g_xr[(size_t)BB * HW * CI];      // NHWC fp16 input (16 MB)
__device__ __half g_wt[(size_t)BB * 9 * CO * CI];  // [b][rs][cout][cin] fp16 (4.7 MB)
__device__ unsigned int g_cnt[BB];                 // per-sample prep counters

__device__ __forceinline__ uint32_t smem_u32(const void* p) {
    uint32_t a; asm("{ .reg .u64 t; cvta.to.shared.u64 t, %1; cvt.u32.u64 %0, t; }" : "=r"(a) : "l"(p));
    return a;
}
__device__ __forceinline__ void ldm_x4(uint32_t* r, uint32_t addr) {
    asm volatile("ldmatrix.sync.aligned.m8n8.x4.shared.b16 {%0,%1,%2,%3}, [%4];"
                 : "=r"(r[0]), "=r"(r[1]), "=r"(r[2]), "=r"(r[3]) : "r"(addr));
}

// ---- main fused kernel ----
static constexpr int AP = 72;                          // 64 halves + 8 pad (144 B rows)
static constexpr int A_HALVES = 128 * AP;              // 9216
static constexpr int B_HALVES = 128 * AP;              // 9216
static constexpr int STG = A_HALVES + B_HALVES;        // 18432 halves (36864 B)
static constexpr int SMEM_BYTES = 3 * STG * 2;         // 110592 B / CTA

__global__ __launch_bounds__(256, 2) void conv_kernel(const float* __restrict__ x,
                                                      const float* __restrict__ wk,
                                                      float* __restrict__ out) {
    extern __shared__ __half sm[];
    const uint32_t sb = smem_u32(sm);
    const int tid = threadIdx.x, wid = tid >> 5, lane = tid & 31;
    const int bid = blockIdx.x;
    const int b = bid >> 5, nt = bid & 31;

    // ================= prep phase: CTAs 0..255 do 5 units each =================
    if (bid < 256) {
        for (int j = 0; j < 5; ++j) {
            const int unit = bid * 5 + j;
            const int s = unit / 80, r = unit - s * 80;   // sample, unit-in-sample
            if (r < 64) {
                // --- x-transpose unit: sample s, image row h=r: NCHW -> NHWC fp16
                float (*t)[129] = (float(*)[129])sm;
                const int h = r;
                const float* src = x + (size_t)s * CI * HW + h * 64;
                for (int c0 = 0; c0 < CI; c0 += 4) {
                    int c = c0 + (tid >> 6), wpos = tid & 63;
                    t[wpos][c] = src[(size_t)c * HW + wpos];
                }
                __syncthreads();
                __half* dst = g_xr + ((size_t)s * 64 + h) * 64 * CI;
                for (int w0 = 0; w0 < 64; w0 += 2) {
                    int wpos = w0 + (tid >> 7), c = tid & 127;
                    dst[(size_t)wpos * CI + c] = __float2half(t[wpos][c]);
                }
            } else {
                // --- weight repack unit: sample s, cout-group cg (8 couts)
                float* tw = (float*)sm;                    // 8*1152*4 = 36864 B
                const int cg = r - 64;
                const float* src = wk + ((size_t)(s * CO + cg * 8)) * 1152;
                for (int i = tid; i < 8 * 1152; i += 256) tw[i] = src[i];
                __syncthreads();
                for (int jj = tid; jj < 8 * 1152; jj += 256) {
                    int rs = jj >> 10, co8 = (jj >> 7) & 7, cin = jj & 127;
                    g_wt[(((size_t)(s * 9 + rs)) * CO + cg * 8 + co8) * CI + cin] =
                        __float2half(tw[co8 * 1152 + cin * 9 + rs]);
                }
            }
            __syncthreads();
            if (tid == 0) { __threadfence(); atomicAdd(&g_cnt[s], 1u); }
            __syncthreads();                               // smem reuse barrier
        }
    }

    // ================= wait for this CTA's sample to be fully prepped ==========
    if (tid == 0) {
        unsigned v;
        do {
            asm volatile("ld.acquire.gpu.u32 %0, [%1];" : "=r"(v) : "l"(&g_cnt[b]) : "memory");
            if (v < 80u) __nanosleep(64);
        } while (v < 80u);
    }
    __syncthreads();

    // ================= conv mainloop (R9) ======================================
    const int h2 = nt << 1;                            // 2 image rows / CTA
    const int mb = (wid & 1) << 6;                     // warp grid: 2 m x 4 n
    const int nb = (wid >> 1) << 5;                    // warp tile 64 x 32
    const int qid = lane >> 2, tig = lane & 3;

    const int ar16 = ((lane >> 3) & 1) * 8 + (lane & 7);   // A: row-in-16
    const int akh  = (lane >> 4) & 1;                      // A: k-half
    const int br16 = ((lane >> 4) & 1) * 8 + (lane & 7);   // B: n-in-16
    const int bkh  = (lane >> 3) & 1;                      // B: k-half

    const __half* xb = g_xr + (size_t)b * HW * CI;
    const __half* wb = g_wt + (size_t)b * 9 * CO * CI;

    float acc[4][4][4];
#pragma unroll
    for (int f = 0; f < 4; f++)
#pragma unroll
        for (int j = 0; j < 4; j++)
#pragma unroll
            for (int c = 0; c < 4; c++) acc[f][j][c] = 0.f;

    auto issue = [&](int it) {
        const int st = it % 3, rs = it >> 1, c0 = (it & 1) << 6;   // cin chunk of 64
        const int rd = rs / 3, r = rd - 1, s = rs - rd * 3 - 1;
        const uint32_t abase = sb + (uint32_t)st * STG * 2;
        const uint32_t bbase = abase + A_HALVES * 2;
        const __half* wrs = wb + (size_t)rs * CO * CI + c0;
#pragma unroll
        for (int t = 0; t < 4; t++) {                  // A: 128m x 64k = 1024 x 16B
            int ci = tid + (t << 8);
            int m = ci >> 3, seg = ci & 7;
            uint32_t d = abase + (uint32_t)(m * AP + seg * 8) * 2;
            const __half* g = wrs + m * CI + seg * 8;
            asm volatile("cp.async.cg.shared.global [%0], [%1], 16;"
                         :: "r"(d), "l"(g) : "memory");
        }
#pragma unroll
        for (int t = 0; t < 4; t++) {                  // B: 128n x 64k, halo-masked
            int ci = tid + (t << 8);
            int n = ci >> 3, seg = ci & 7;
            int h = h2 + (n >> 6) + r, w = (n & 63) + s;
            bool ok = ((unsigned)h < 64u) && ((unsigned)w < 64u);
            int hc = ok ? h : 0, wc = ok ? w : 0;
            int sz = ok ? 16 : 0;
            uint32_t d = bbase + (uint32_t)(n * AP + seg * 8) * 2;
            const __half* g = xb + (size_t)((hc << 6) + wc) * CI + c0 + seg * 8;
            asm volatile("cp.async.cg.shared.global [%0], [%1], 16, %2;"
                         :: "r"(d), "l"(g), "r"(sz) : "memory");
        }
    };

    issue(0); asm volatile("cp.async.commit_group;" ::: "memory");
    issue(1); asm volatile("cp.async.commit_group;" ::: "memory");

    for (int it = 0; it < 18; ++it) {
        asm volatile("cp.async.wait_group 1;" ::: "memory");
        __syncthreads();
        if (it < 16) issue(it + 2);
        asm volatile("cp.async.commit_group;" ::: "memory");

        const int st = it % 3;
        const uint32_t abase = sb + (uint32_t)st * STG * 2;
        const uint32_t bbase = abase + A_HALVES * 2;
        const uint32_t a0 = abase + (uint32_t)((mb + ar16) * AP + akh * 8) * 2;
        const uint32_t b0 = bbase + (uint32_t)((nb + br16) * AP + bkh * 8) * 2;

#pragma unroll
        for (int ks = 0; ks < 4; ++ks) {               // four k16 slices
            uint32_t a[4][4], bq[2][4];
#pragma unroll
            for (int f = 0; f < 4; ++f)
                ldm_x4(a[f], a0 + (uint32_t)(f * 16 * AP + ks * 16) * 2);
#pragma unroll
            for (int jj = 0; jj < 2; ++jj)
                ldm_x4(bq[jj], b0 + (uint32_t)(jj * 16 * AP + ks * 16) * 2);
#pragma unroll
            for (int f = 0; f < 4; ++f)
#pragma unroll
                for (int jj = 0; jj < 2; ++jj) {
                    asm volatile(
                        "mma.sync.aligned.m16n8k16.row.col.f32.f16.f16.f32 "
                        "{%0,%1,%2,%3}, {%4,%5,%6,%7}, {%8,%9}, {%0,%1,%2,%3};"
                        : "+f"(acc[f][2 * jj][0]), "+f"(acc[f][2 * jj][1]),
                          "+f"(acc[f][2 * jj][2]), "+f"(acc[f][2 * jj][3])
                        : "r"(a[f][0]), "r"(a[f][1]), "r"(a[f][2]), "r"(a[f][3]),
                          "r"(bq[jj][0]), "r"(bq[jj][1]));
                    asm volatile(
                        "mma.sync.aligned.m16n8k16.row.col.f32.f16.f16.f32 "
                        "{%0,%1,%2,%3}, {%4,%5,%6,%7}, {%8,%9}, {%0,%1,%2,%3};"
                        : "+f"(acc[f][2 * jj + 1][0]), "+f"(acc[f][2 * jj + 1][1]),
                          "+f"(acc[f][2 * jj + 1][2]), "+f"(acc[f][2 * jj + 1][3])
                        : "r"(a[f][0]), "r"(a[f][1]), "r"(a[f][2]), "r"(a[f][3]),
                          "r"(bq[jj][2]), "r"(bq[jj][3]));
                }
        }
    }

    // epilogue: warp covers 64 m x 32 n of the 128x128 tile
#pragma unroll
    for (int f = 0; f < 4; ++f) {
        int co = mb + 16 * f + qid;
        float* o0 = out + ((size_t)(b * CO + co)) * HW + (nt << 7) + nb + 2 * tig;
        float* o1 = o0 + 8 * HW;
#pragma unroll
        for (int j = 0; j < 4; ++j) {
            *(float2*)(o0 + 8 * j) = make_float2(acc[f][j][0], acc[f][j][1]);
            *(float2*)(o1 + 8 * j) = make_float2(acc[f][j][2], acc[f][j][3]);
        }
    }
}

extern "C" void kernel_launch(void* const* d_in, const int* in_sizes, int n_in,
                              void* d_out, int out_size) {
    const float* feat = (const float*)d_in[0];   // (16,128,64,64)
    const float* wker = (const float*)d_in[1];   // (16,128,128,3,3)
    float* out = (float*)d_out;

    cudaFuncSetAttribute(conv_kernel, cudaFuncAttributeMaxDynamicSharedMemorySize, SMEM_BYTES);

    void* cptr = nullptr;
    cudaGetSymbolAddress(&cptr, g_cnt);
    cudaMemsetAsync(cptr, 0, sizeof(unsigned int) * BB);

    conv_kernel<<<512, 256, SMEM_BYTES>>>(feat, wker, out);
}

// round 12
// speedup vs baseline: 1.1422x; 1.1422x over previous
#include <cuda_runtime.h>
#include <cuda_fp16.h>
#include <cstdint>

// DynamicConvolution: B=16, Cin=Cout=128, K=3, H=W=64, pad=1, fp32.
// R11: fused prep+conv, fixed. Prep units round-robin across all 256 prep CTAs
// (unit = j*256 + bid) so early samples complete first and conv pipelines in.
// Spin-wait uses relaxed polls + single acquire. Conv mainloop identical to R9
// (fp16 m16n8k16, K-chunk 64, 3-stage cp.async, 2 CTAs/SM, 128x128 tiles).

#define BB 16
#define CI 128
#define CO 128
#define HW 4096

__device__ __half g_xr[(size_t)BB * HW * CI];      // NHWC fp16 input (16 MB)
__device__ __half g_wt[(size_t)BB * 9 * CO * CI];  // [b][rs][cout][cin] fp16 (4.7 MB)
__device__ unsigned int g_cnt[BB];                 // per-sample prep counters

__device__ __forceinline__ uint32_t smem_u32(const void* p) {
    uint32_t a; asm("{ .reg .u64 t; cvta.to.shared.u64 t, %1; cvt.u32.u64 %0, t; }" : "=r"(a) : "l"(p));
    return a;
}
__device__ __forceinline__ void ldm_x4(uint32_t* r, uint32_t addr) {
    asm volatile("ldmatrix.sync.aligned.m8n8.x4.shared.b16 {%0,%1,%2,%3}, [%4];"
                 : "=r"(r[0]), "=r"(r[1]), "=r"(r[2]), "=r"(r[3]) : "r"(addr));
}

static constexpr int AP = 72;                          // 64 halves + 8 pad (144 B rows)
static constexpr int A_HALVES = 128 * AP;              // 9216
static constexpr int B_HALVES = 128 * AP;              // 9216
static constexpr int STG = A_HALVES + B_HALVES;        // 18432 halves (36864 B)
static constexpr int SMEM_BYTES = 3 * STG * 2;         // 110592 B / CTA

__global__ __launch_bounds__(256, 2) void conv_kernel(const float* __restrict__ x,
                                                      const float* __restrict__ wk,
                                                      float* __restrict__ out) {
    extern __shared__ __half sm[];
    const uint32_t sb = smem_u32(sm);
    const int tid = threadIdx.x, wid = tid >> 5, lane = tid & 31;
    const int bid = blockIdx.x;
    const int b = bid >> 5, nt = bid & 31;

    // ====== prep phase: 1280 units, round-robin over CTAs 0..255 ======
    // unit = j*256 + bid  ->  slice j=0 covers samples 0..3 in parallel, etc.
    if (bid < 256) {
        for (int j = 0; j < 5; ++j) {
            const int unit = j * 256 + bid;
            const int s = unit / 80, r = unit - s * 80;   // sample, unit-in-sample
            if (r < 64) {
                // x-transpose unit: sample s, image row h=r: NCHW -> NHWC fp16
                float (*t)[129] = (float(*)[129])sm;
                const int h = r;
                const float* src = x + (size_t)s * CI * HW + h * 64;
                for (int c0 = 0; c0 < CI; c0 += 4) {
                    int c = c0 + (tid >> 6), wpos = tid & 63;
                    t[wpos][c] = src[(size_t)c * HW + wpos];
                }
                __syncthreads();
                __half* dst = g_xr + ((size_t)s * 64 + h) * 64 * CI;
                for (int w0 = 0; w0 < 64; w0 += 2) {
                    int wpos = w0 + (tid >> 7), c = tid & 127;
                    dst[(size_t)wpos * CI + c] = __float2half(t[wpos][c]);
                }
            } else {
                // weight repack unit: sample s, cout-group cg (8 couts)
                float* tw = (float*)sm;                    // 8*1152*4 = 36864 B
                const int cg = r - 64;
                const float* src = wk + ((size_t)(s * CO + cg * 8)) * 1152;
                for (int i = tid; i < 8 * 1152; i += 256) tw[i] = src[i];
                __syncthreads();
                for (int jj = tid; jj < 8 * 1152; jj += 256) {
                    int rs = jj >> 10, co8 = (jj >> 7) & 7, cin = jj & 127;
                    g_wt[(((size_t)(s * 9 + rs)) * CO + cg * 8 + co8) * CI + cin] =
                        __float2half(tw[co8 * 1152 + cin * 9 + rs]);
                }
            }
            __syncthreads();
            if (tid == 0) { __threadfence(); atomicAdd(&g_cnt[s], 1u); }
            __syncthreads();                               // smem reuse barrier
        }
    }

    // ====== wait for this CTA's sample: relaxed polls, one final acquire ======
    if (tid == 0) {
        unsigned v;
        do {
            asm volatile("ld.relaxed.gpu.u32 %0, [%1];" : "=r"(v) : "l"(&g_cnt[b]) : "memory");
            if (v < 80u) __nanosleep(128);
        } while (v < 80u);
        asm volatile("ld.acquire.gpu.u32 %0, [%1];" : "=r"(v) : "l"(&g_cnt[b]) : "memory");
    }
    __syncthreads();

    // ====== conv mainloop (identical to R9) ======
    const int h2 = nt << 1;                            // 2 image rows / CTA
    const int mb = (wid & 1) << 6;                     // warp grid: 2 m x 4 n
    const int nb = (wid >> 1) << 5;                    // warp tile 64 x 32
    const int qid = lane >> 2, tig = lane & 3;

    const int ar16 = ((lane >> 3) & 1) * 8 + (lane & 7);   // A: row-in-16
    const int akh  = (lane >> 4) & 1;                      // A: k-half
    const int br16 = ((lane >> 4) & 1) * 8 + (lane & 7);   // B: n-in-16
    const int bkh  = (lane >> 3) & 1;                      // B: k-half

    const __half* xb = g_xr + (size_t)b * HW * CI;
    const __half* wb = g_wt + (size_t)b * 9 * CO * CI;

    float acc[4][4][4];
#pragma unroll
    for (int f = 0; f < 4; f++)
#pragma unroll
        for (int j = 0; j < 4; j++)
#pragma unroll
            for (int c = 0; c < 4; c++) acc[f][j][c] = 0.f;

    auto issue = [&](int it) {
        const int st = it % 3, rs = it >> 1, c0 = (it & 1) << 6;   // cin chunk of 64
        const int rd = rs / 3, r = rd - 1, s = rs - rd * 3 - 1;
        const uint32_t abase = sb + (uint32_t)st * STG * 2;
        const uint32_t bbase = abase + A_HALVES * 2;
        const __half* wrs = wb + (size_t)rs * CO * CI + c0;
#pragma unroll
        for (int t = 0; t < 4; t++) {                  // A: 128m x 64k = 1024 x 16B
            int ci = tid + (t << 8);
            int m = ci >> 3, seg = ci & 7;
            uint32_t d = abase + (uint32_t)(m * AP + seg * 8) * 2;
            const __half* g = wrs + m * CI + seg * 8;
            asm volatile("cp.async.cg.shared.global [%0], [%1], 16;"
                         :: "r"(d), "l"(g) : "memory");
        }
#pragma unroll
        for (int t = 0; t < 4; t++) {                  // B: 128n x 64k, halo-masked
            int ci = tid + (t << 8);
            int n = ci >> 3, seg = ci & 7;
            int h = h2 + (n >> 6) + r, w = (n & 63) + s;
            bool ok = ((unsigned)h < 64u) && ((unsigned)w < 64u);
            int hc = ok ? h : 0, wc = ok ? w : 0;
            int sz = ok ? 16 : 0;
            uint32_t d = bbase + (uint32_t)(n * AP + seg * 8) * 2;
            const __half* g = xb + (size_t)((hc << 6) + wc) * CI + c0 + seg * 8;
            asm volatile("cp.async.cg.shared.global [%0], [%1], 16, %2;"
                         :: "r"(d), "l"(g), "r"(sz) : "memory");
        }
    };

    issue(0); asm volatile("cp.async.commit_group;" ::: "memory");
    issue(1); asm volatile("cp.async.commit_group;" ::: "memory");

    for (int it = 0; it < 18; ++it) {
        asm volatile("cp.async.wait_group 1;" ::: "memory");
        __syncthreads();
        if (it < 16) issue(it + 2);
        asm volatile("cp.async.commit_group;" ::: "memory");

        const int st = it % 3;
        const uint32_t abase = sb + (uint32_t)st * STG * 2;
        const uint32_t bbase = abase + A_HALVES * 2;
        const uint32_t a0 = abase + (uint32_t)((mb + ar16) * AP + akh * 8) * 2;
        const uint32_t b0 = bbase + (uint32_t)((nb + br16) * AP + bkh * 8) * 2;

#pragma unroll
        for (int ks = 0; ks < 4; ++ks) {               // four k16 slices
            uint32_t a[4][4], bq[2][4];
#pragma unroll
            for (int f = 0; f < 4; ++f)
                ldm_x4(a[f], a0 + (uint32_t)(f * 16 * AP + ks * 16) * 2);
#pragma unroll
            for (int jj = 0; jj < 2; ++jj)
                ldm_x4(bq[jj], b0 + (uint32_t)(jj * 16 * AP + ks * 16) * 2);
#pragma unroll
            for (int f = 0; f < 4; ++f)
#pragma unroll
                for (int jj = 0; jj < 2; ++jj) {
                    asm volatile(
                        "mma.sync.aligned.m16n8k16.row.col.f32.f16.f16.f32 "
                        "{%0,%1,%2,%3}, {%4,%5,%6,%7}, {%8,%9}, {%0,%1,%2,%3};"
                        : "+f"(acc[f][2 * jj][0]), "+f"(acc[f][2 * jj][1]),
                          "+f"(acc[f][2 * jj][2]), "+f"(acc[f][2 * jj][3])
                        : "r"(a[f][0]), "r"(a[f][1]), "r"(a[f][2]), "r"(a[f][3]),
                          "r"(bq[jj][0]), "r"(bq[jj][1]));
                    asm volatile(
                        "mma.sync.aligned.m16n8k16.row.col.f32.f16.f16.f32 "
                        "{%0,%1,%2,%3}, {%4,%5,%6,%7}, {%8,%9}, {%0,%1,%2,%3};"
                        : "+f"(acc[f][2 * jj + 1][0]), "+f"(acc[f][2 * jj + 1][1]),
                          "+f"(acc[f][2 * jj + 1][2]), "+f"(acc[f][2 * jj + 1][3])
                        : "r"(a[f][0]), "r"(a[f][1]), "r"(a[f][2]), "r"(a[f][3]),
                          "r"(bq[jj][2]), "r"(bq[jj][3]));
                }
        }
    }

    // epilogue: warp covers 64 m x 32 n of the 128x128 tile
#pragma unroll
    for (int f = 0; f < 4; ++f) {
        int co = mb + 16 * f + qid;
        float* o0 = out + ((size_t)(b * CO + co)) * HW + (nt << 7) + nb + 2 * tig;
        float* o1 = o0 + 8 * HW;
#pragma unroll
        for (int j = 0; j < 4; ++j) {
            *(float2*)(o0 + 8 * j) = make_float2(acc[f][j][0], acc[f][j][1]);
            *(float2*)(o1 + 8 * j) = make_float2(acc[f][j][2], acc[f][j][3]);
        }
    }
}

extern "C" void kernel_launch(void* const* d_in, const int* in_sizes, int n_in,
                              void* d_out, int out_size) {
    const float* feat = (const float*)d_in[0];   // (16,128,64,64)
    const float* wker = (const float*)d_in[1];   // (16,128,128,3,3)
    float* out = (float*)d_out;

    cudaFuncSetAttribute(conv_kernel, cudaFuncAttributeMaxDynamicSharedMemorySize, SMEM_BYTES);

    void* cptr = nullptr;
    cudaGetSymbolAddress(&cptr, g_cnt);
    cudaMemsetAsync(cptr, 0, sizeof(unsigned int) * BB);

    conv_kernel<<<512, 256, SMEM_BYTES>>>(feat, wker, out);
}